// round 16
// baseline (speedup 1.0000x reference)
#include <cuda_runtime.h>

// SIREN: N pts, 3 -> 5 (sine) -> 256 x [5 -> 5 (sine)] -> 1 linear.
// Output: [out (N) | coords passthrough (3N)].
// 4 pts/thread as 2 f32x2 packs, k-step interleaved layers, TPB=128/grid=1024.
// SINE SPLIT 2:8 poly:MUFU — 2 of 10 sine-packs per layer computed by an
// FMA-pipe polynomial (CW mod-pi + deg-9 minimax), lowering the MUFU floor
// from 160 to 128 SMSP-cyc/warp-layer while FMA rises to 140 (new balance).

typedef unsigned long long u64;
typedef unsigned int u32;

static constexpr int IN_F  = 3;
static constexpr int HID   = 5;
static constexpr int N_HID = 256;
static constexpr float OMEGA = 30.0f;
static constexpr int TPB = 128;

// smem: [0, 51200) 256 layers x 25 w dup-pairs (u64); [51200, 56320) 256 x 5 bias scalars
static constexpr int BLOB_U64   = N_HID * 25;
static constexpr int SMEM_BYTES = BLOB_U64 * 8 + N_HID * 5 * 4;   // 56320

__device__ __forceinline__ u64 fma2(u64 a, u64 b, u64 c) {
    u64 d; asm("fma.rn.f32x2 %0, %1, %2, %3;" : "=l"(d) : "l"(a), "l"(b), "l"(c)); return d;
}
__device__ __forceinline__ u64 add2(u64 a, u64 b) {
    u64 d; asm("add.rn.f32x2 %0, %1, %2;" : "=l"(d) : "l"(a), "l"(b)); return d;
}
__device__ __forceinline__ u64 mul2(u64 a, u64 b) {
    u64 d; asm("mul.rn.f32x2 %0, %1, %2;" : "=l"(d) : "l"(a), "l"(b)); return d;
}
__device__ __forceinline__ u64 pack2(float a, float b) {
    u64 d; asm("mov.b64 %0, {%1, %2};" : "=l"(d) : "f"(a), "f"(b)); return d;
}
__device__ __forceinline__ u64 splat2(float a) {
    u64 d; asm("mov.b64 %0, {%1, %1};" : "=l"(d) : "f"(a)); return d;
}
__device__ __forceinline__ float2 unpack2(u64 d) {
    float2 f; asm("mov.b64 {%0, %1}, %2;" : "=f"(f.x), "=f"(f.y) : "l"(d)); return f;
}
__device__ __forceinline__ float sinap(float x) {
    float s; asm("sin.approx.f32 %0, %1;" : "=f"(s) : "f"(x)); return s;
}

// MUFU sine of both packed lanes (hardware range reduction, |y| <= ~19).
__device__ __forceinline__ u64 sin2m(u64 y) {
    float2 f = unpack2(y);
    return pack2(sinap(f.x), sinap(f.y));
}

// Poly-sine constants (mod-pi reduction, deg-9 minimax on [-pi/2,pi/2]).
struct SinK { u64 magic, nmagic, invpi, npi1, npi2, c9, c7, c5, c3; };

// FMA-pipe sine of both packed lanes: fj = rint(y/pi) via magic add,
// r = y - fj*pi (2-term CW), deg-9 odd minimax, sign flip (-1)^fj via
// parity bit of the magic-biased value (ALU pipe).
__device__ __forceinline__ u64 sin2p(u64 y, const SinK& K) {
    u64 t  = fma2(y, K.invpi, K.magic);
    u64 fj = add2(t, K.nmagic);
    u64 r  = fma2(fj, K.npi1, y);
    r      = fma2(fj, K.npi2, r);
    u64 r2 = mul2(r, r);
    u64 p  = fma2(r2, K.c9, K.c7);
    p      = fma2(r2, p, K.c5);
    p      = fma2(r2, p, K.c3);
    u64 r3 = mul2(r, r2);
    u64 s  = fma2(r3, p, r);
    u32 slo = (u32)s         ^ ((u32)t         << 31);
    u32 shi = (u32)(s >> 32) ^ ((u32)(t >> 32) << 31);
    return ((u64)shi << 32) | slo;
}

// One layer, k-step interleaved; sine split: k=0 stream-A and k=3 stream-B use poly.
#define LAYER(A0,A1,A2,A3,A4, P0,P1,P2,P3,P4,                         \
              O0,O1,O2,O3,O4, Q0,Q1,Q2,Q3,Q4, Lp, Bp)                 \
{                                                                     \
    u64 s, t, w, bb;                                                  \
    s = sin2p(A0, K); t = sin2m(P0);                                  \
    bb = splat2((Bp)[0]); w = (Lp)[ 0]; O0 = fma2(w, s, bb); Q0 = fma2(w, t, bb); \
    bb = splat2((Bp)[1]); w = (Lp)[ 1]; O1 = fma2(w, s, bb); Q1 = fma2(w, t, bb); \
    bb = splat2((Bp)[2]); w = (Lp)[ 2]; O2 = fma2(w, s, bb); Q2 = fma2(w, t, bb); \
    bb = splat2((Bp)[3]); w = (Lp)[ 3]; O3 = fma2(w, s, bb); Q3 = fma2(w, t, bb); \
    bb = splat2((Bp)[4]); w = (Lp)[ 4]; O4 = fma2(w, s, bb); Q4 = fma2(w, t, bb); \
    s = sin2m(A1); t = sin2m(P1);                                     \
    w = (Lp)[ 5]; O0 = fma2(w, s, O0); Q0 = fma2(w, t, Q0);           \
    w = (Lp)[ 6]; O1 = fma2(w, s, O1); Q1 = fma2(w, t, Q1);           \
    w = (Lp)[ 7]; O2 = fma2(w, s, O2); Q2 = fma2(w, t, Q2);           \
    w = (Lp)[ 8]; O3 = fma2(w, s, O3); Q3 = fma2(w, t, Q3);           \
    w = (Lp)[ 9]; O4 = fma2(w, s, O4); Q4 = fma2(w, t, Q4);           \
    s = sin2m(A2); t = sin2m(P2);                                     \
    w = (Lp)[10]; O0 = fma2(w, s, O0); Q0 = fma2(w, t, Q0);           \
    w = (Lp)[11]; O1 = fma2(w, s, O1); Q1 = fma2(w, t, Q1);           \
    w = (Lp)[12]; O2 = fma2(w, s, O2); Q2 = fma2(w, t, Q2);           \
    w = (Lp)[13]; O3 = fma2(w, s, O3); Q3 = fma2(w, t, Q3);           \
    w = (Lp)[14]; O4 = fma2(w, s, O4); Q4 = fma2(w, t, Q4);           \
    s = sin2m(A3); t = sin2p(P3, K);                                  \
    w = (Lp)[15]; O0 = fma2(w, s, O0); Q0 = fma2(w, t, Q0);           \
    w = (Lp)[16]; O1 = fma2(w, s, O1); Q1 = fma2(w, t, Q1);           \
    w = (Lp)[17]; O2 = fma2(w, s, O2); Q2 = fma2(w, t, Q2);           \
    w = (Lp)[18]; O3 = fma2(w, s, O3); Q3 = fma2(w, t, Q3);           \
    w = (Lp)[19]; O4 = fma2(w, s, O4); Q4 = fma2(w, t, Q4);           \
    s = sin2m(A4); t = sin2m(P4);                                     \
    w = (Lp)[20]; O0 = fma2(w, s, O0); Q0 = fma2(w, t, Q0);           \
    w = (Lp)[21]; O1 = fma2(w, s, O1); Q1 = fma2(w, t, Q1);           \
    w = (Lp)[22]; O2 = fma2(w, s, O2); Q2 = fma2(w, t, Q2);           \
    w = (Lp)[23]; O3 = fma2(w, s, O3); Q3 = fma2(w, t, Q3);           \
    w = (Lp)[24]; O4 = fma2(w, s, O4); Q4 = fma2(w, t, Q4);           \
}

__global__ void __launch_bounds__(TPB, 4)
siren_kernel(const float* __restrict__ coords,
             const float* __restrict__ Wf, const float* __restrict__ bf,
             const float* __restrict__ Wh, const float* __restrict__ bh,
             const float* __restrict__ Wl, const float* __restrict__ bl,
             float* __restrict__ out, int N)
{
    extern __shared__ float smem[];
    u64*   wp = (u64*)smem;                  // 25 pairs per layer
    float* bp = smem + BLOB_U64 * 2;         // 5 scalars per layer

    const int tid = threadIdx.x;
    for (int idx = tid; idx < N_HID * 25; idx += TPB) {
        int l = idx / 25, r = idx % 25;
        int j = r / 5, k = r % 5;
        wp[l * 25 + k * 5 + j] = splat2(OMEGA * Wh[l * 25 + j * 5 + k]);
    }
    for (int idx = tid; idx < N_HID * 5; idx += TPB) {
        bp[idx] = OMEGA * bh[idx];
    }
    __syncthreads();

    const int g = blockIdx.x * TPB + tid;    // quad index: points 4g..4g+3

    SinK K;
    K.magic  = splat2( 12582912.0f);
    K.nmagic = splat2(-12582912.0f);
    K.invpi  = splat2( 0.318309886183790672f);
    K.npi1   = splat2(-3.14159250259399414e+0f);
    K.npi2   = splat2(-1.50995788317173719e-7f);
    K.c9     = splat2( 2.7183114939898219e-6f);
    K.c7     = splat2(-1.9839334836096632e-4f);
    K.c5     = splat2( 8.3333293858894632e-3f);
    K.c3     = splat2(-1.6666666641626524e-1f);

    // coords: 12 consecutive floats -> 3x LDG.128; passthrough stored immediately
    const float4* c4p = (const float4*)coords;
    float4 q0 = c4p[3 * g + 0];
    float4 q1 = c4p[3 * g + 1];
    float4 q2 = c4p[3 * g + 2];
    float4* cpass = (float4*)(out + N);
    cpass[3 * g + 0] = q0;
    cpass[3 * g + 1] = q1;
    cpass[3 * g + 2] = q2;

    u64 a_c0 = pack2(q0.x, q0.w);  // stream A: points 0,1
    u64 a_c1 = pack2(q0.y, q1.x);
    u64 a_c2 = pack2(q0.z, q1.y);
    u64 b_c0 = pack2(q1.z, q2.y);  // stream B: points 2,3
    u64 b_c1 = pack2(q1.w, q2.z);
    u64 b_c2 = pack2(q2.x, q2.w);

    // ---- warp desync: stagger co-resident blocks ----
    {
        int slot = blockIdx.x & 3;
        int iters = slot * 16;
        float v = (float)tid;
#pragma unroll 1
        for (int i = 0; i < iters; i++) v += 1.0f;
        asm volatile("" :: "f"(v));
    }

    // first layer -> pre-activations ya*/yb*
    u64 ya0, ya1, ya2, ya3, ya4, yb0, yb1, yb2, yb3, yb4;
    {
        u64 w, bj;
        bj = splat2(OMEGA * bf[0]);
        w = splat2(OMEGA * Wf[0]);  ya0 = fma2(w, a_c0, bj); yb0 = fma2(w, b_c0, bj);
        w = splat2(OMEGA * Wf[1]);  ya0 = fma2(w, a_c1, ya0); yb0 = fma2(w, b_c1, yb0);
        w = splat2(OMEGA * Wf[2]);  ya0 = fma2(w, a_c2, ya0); yb0 = fma2(w, b_c2, yb0);
        bj = splat2(OMEGA * bf[1]);
        w = splat2(OMEGA * Wf[3]);  ya1 = fma2(w, a_c0, bj); yb1 = fma2(w, b_c0, bj);
        w = splat2(OMEGA * Wf[4]);  ya1 = fma2(w, a_c1, ya1); yb1 = fma2(w, b_c1, yb1);
        w = splat2(OMEGA * Wf[5]);  ya1 = fma2(w, a_c2, ya1); yb1 = fma2(w, b_c2, yb1);
        bj = splat2(OMEGA * bf[2]);
        w = splat2(OMEGA * Wf[6]);  ya2 = fma2(w, a_c0, bj); yb2 = fma2(w, b_c0, bj);
        w = splat2(OMEGA * Wf[7]);  ya2 = fma2(w, a_c1, ya2); yb2 = fma2(w, b_c1, yb2);
        w = splat2(OMEGA * Wf[8]);  ya2 = fma2(w, a_c2, ya2); yb2 = fma2(w, b_c2, yb2);
        bj = splat2(OMEGA * bf[3]);
        w = splat2(OMEGA * Wf[9]);  ya3 = fma2(w, a_c0, bj); yb3 = fma2(w, b_c0, bj);
        w = splat2(OMEGA * Wf[10]); ya3 = fma2(w, a_c1, ya3); yb3 = fma2(w, b_c1, yb3);
        w = splat2(OMEGA * Wf[11]); ya3 = fma2(w, a_c2, ya3); yb3 = fma2(w, b_c2, yb3);
        bj = splat2(OMEGA * bf[4]);
        w = splat2(OMEGA * Wf[12]); ya4 = fma2(w, a_c0, bj); yb4 = fma2(w, b_c0, bj);
        w = splat2(OMEGA * Wf[13]); ya4 = fma2(w, a_c1, ya4); yb4 = fma2(w, b_c1, yb4);
        w = splat2(OMEGA * Wf[14]); ya4 = fma2(w, a_c2, ya4); yb4 = fma2(w, b_c2, yb4);
    }

    // 256 hidden layers = 128 x 2 (double-buffer role swap, no copies)
    u64 na0, na1, na2, na3, na4, nb0, nb1, nb2, nb3, nb4;
    const u64*   L = wp;
    const float* B = bp;
#pragma unroll 1
    for (int i = 0; i < N_HID / 2; i++) {
        LAYER(ya0,ya1,ya2,ya3,ya4, yb0,yb1,yb2,yb3,yb4,
              na0,na1,na2,na3,na4, nb0,nb1,nb2,nb3,nb4, L, B)
        LAYER(na0,na1,na2,na3,na4, nb0,nb1,nb2,nb3,nb4,
              ya0,ya1,ya2,ya3,ya4, yb0,yb1,yb2,yb3,yb4, L + 25, B + 5)
        L += 50;
        B += 10;
    }

    // final: sin of last pre-acts, then linear (weights direct from global)
    u64 oa = splat2(bl[0]), ob = oa;
    {
        u64 w, s, t;
        w = splat2(Wl[0]); s = sin2m(ya0); t = sin2m(yb0);
        oa = fma2(w, s, oa); ob = fma2(w, t, ob);
        w = splat2(Wl[1]); s = sin2m(ya1); t = sin2m(yb1);
        oa = fma2(w, s, oa); ob = fma2(w, t, ob);
        w = splat2(Wl[2]); s = sin2m(ya2); t = sin2m(yb2);
        oa = fma2(w, s, oa); ob = fma2(w, t, ob);
        w = splat2(Wl[3]); s = sin2m(ya3); t = sin2m(yb3);
        oa = fma2(w, s, oa); ob = fma2(w, t, ob);
        w = splat2(Wl[4]); s = sin2m(ya4); t = sin2m(yb4);
        oa = fma2(w, s, oa); ob = fma2(w, t, ob);
    }

    float2 fa = unpack2(oa), fb = unpack2(ob);
    ((float4*)out)[g] = make_float4(fa.x, fa.y, fb.x, fb.y);
}

extern "C" void kernel_launch(void* const* d_in, const int* in_sizes, int n_in,
                              void* d_out, int out_size)
{
    const float* coords = (const float*)d_in[0];
    const float* Wf     = (const float*)d_in[1];
    const float* bf     = (const float*)d_in[2];
    const float* Wh     = (const float*)d_in[3];
    const float* bh     = (const float*)d_in[4];
    const float* Wl     = (const float*)d_in[5];
    const float* bl     = (const float*)d_in[6];
    float* out = (float*)d_out;

    const int N = in_sizes[0] / IN_F;               // 524288
    const int quads = N / 4;                        // 131072
    const int blocks = quads / TPB;                 // 1024, exact

    cudaFuncSetAttribute(siren_kernel, cudaFuncAttributeMaxDynamicSharedMemorySize, SMEM_BYTES);
    siren_kernel<<<blocks, TPB, SMEM_BYTES>>>(coords, Wf, bf, Wh, bh, Wl, bl, out, N);
}